// round 11
// baseline (speedup 1.0000x reference)
#include <cuda_runtime.h>
#include <math.h>
#include <stdint.h>

#define N_NODES 100000
#define N_EDGES 640000
#define N_FEAT  128

#define SCAN_CHUNK 512
#define N_CHUNKS ((N_NODES + SCAN_CHUNK - 1) / SCAN_CHUNK)   // 196

// ---------------- scratch (device globals; zero-initialized at load) -------
__device__ int   g_cnt[N_NODES];        // invariant: zero at start of each call
__device__ int   g_offs[N_NODES];
__device__ int   g_cursor[N_NODES];
__device__ int2  g_edge[N_EDGES];       // (src, bits(dinv[src]))
__device__ int   g_partial[N_CHUNKS];
__device__ float g_dinv[N_NODES];

// fp32 -> tf32 (round-to-nearest) kept in a b32 register
__device__ __forceinline__ uint32_t f2tf32(float f) {
    uint32_t r;
    asm("cvt.rna.tf32.f32 %0, %1;" : "=r"(r) : "f"(f));
    return r;
}

// ---------------------------------------------------------------------------
// 1) histogram of edge destinations (g_cnt starts zeroed)
__global__ void k_hist(const int* __restrict__ ei) {
    int e = blockIdx.x * blockDim.x + threadIdx.x;
    if (e < N_EDGES) atomicAdd(&g_cnt[ei[N_EDGES + e]], 1);
}

// 2a) per-chunk exclusive scan, record chunk totals
__global__ __launch_bounds__(SCAN_CHUNK) void k_scan1() {
    __shared__ int s[SCAN_CHUNK];
    int t = threadIdx.x;
    int gid = blockIdx.x * SCAN_CHUNK + t;
    int v = (gid < N_NODES) ? g_cnt[gid] : 0;
    s[t] = v;
    __syncthreads();
#pragma unroll
    for (int d = 1; d < SCAN_CHUNK; d <<= 1) {
        int add = (t >= d) ? s[t - d] : 0;
        __syncthreads();
        s[t] += add;
        __syncthreads();
    }
    if (gid < N_NODES) g_offs[gid] = s[t] - v;
    if (t == SCAN_CHUNK - 1) g_partial[blockIdx.x] = s[t];
}

// 2b) add chunk base (each block reduces the partials itself); cursor; dinv
__global__ __launch_bounds__(SCAN_CHUNK) void k_scan3() {
    __shared__ int sp[16];
    int c = blockIdx.x;
    int t = threadIdx.x;
    int v = (t < c) ? g_partial[t] : 0;   // c < N_CHUNKS <= 512
#pragma unroll
    for (int o = 16; o; o >>= 1) v += __shfl_xor_sync(0xffffffffu, v, o);
    if ((t & 31) == 0) sp[t >> 5] = v;
    __syncthreads();
    if (t < 32) {
        int u = (t < 16) ? sp[t] : 0;
#pragma unroll
        for (int o = 8; o; o >>= 1) u += __shfl_xor_sync(0xffffffffu, u, o);
        if (t == 0) sp[0] = u;
    }
    __syncthreads();
    int base = sp[0];
    int i = c * SCAN_CHUNK + t;
    if (i < N_NODES) {
        int o = g_offs[i] + base;
        g_offs[i] = o;
        g_cursor[i] = o;
        g_dinv[i] = rsqrtf((float)(g_cnt[i] + 1));
    }
}

// 3) bucket fill: CSR-by-destination, store (src, dinv[src]) per slot
__global__ void k_fill(const int* __restrict__ ei) {
    int e = blockIdx.x * blockDim.x + threadIdx.x;
    if (e >= N_EDGES) return;
    int src = ei[e];
    int dst = ei[N_EDGES + e];
    int pos = atomicAdd(&g_cursor[dst], 1);
    g_edge[pos] = make_int2(src, __float_as_int(g_dinv[src]));
}

// ---------------------------------------------------------------------------
// 4) Fused gather + tf32 tensor-core GEMM + epilogue.
//    Block: 64 nodes, 256 threads (8 warps).
//    smem: A tile 64x128 (tf32), W 128x128 (tf32), 64 row-partials.
#define SA_STRIDE 132
#define SW_STRIDE 132
#define SMEM_A_OFF 0
#define SMEM_W_OFF (64 * SA_STRIDE)
#define SMEM_P_OFF (SMEM_W_OFF + 128 * SW_STRIDE)
#define SMEM_WORDS (SMEM_P_OFF + 64)
#define SMEM_BYTES (SMEM_WORDS * 4)

__global__ __launch_bounds__(256, 2) void k_fused(
    const float* __restrict__ x,
    const float* __restrict__ W,      // [128,128] row-major (out_feat, in_feat)
    const float* __restrict__ bconv,  // [128]
    const float* __restrict__ wlin,   // [128]
    const float* __restrict__ blin,   // [1]
    float* __restrict__ out,          // [N]
    float* __restrict__ h_out)        // [N,128]
{
    extern __shared__ uint32_t sm[];
    uint32_t* sA    = sm + SMEM_A_OFF;
    uint32_t* sW    = sm + SMEM_W_OFF;
    float*    sPart = (float*)(sm + SMEM_P_OFF);

    int tid  = threadIdx.x;
    int lane = tid & 31;
    int w    = tid >> 5;
    int row0 = blockIdx.x * 64;

    if (tid < 64) sPart[tid] = 0.0f;

    // ---- stage W into smem as tf32 (row-major [n][k], conflict-free) ----
    for (int i = tid; i < 128 * 32; i += 256) {
        int n  = i >> 5;
        int k4 = (i & 31) << 2;
        float4 wv = *reinterpret_cast<const float4*>(&W[n * N_FEAT + k4]);
        uint4 tv;
        tv.x = f2tf32(wv.x); tv.y = f2tf32(wv.y);
        tv.z = f2tf32(wv.z); tv.w = f2tf32(wv.w);
        *reinterpret_cast<uint4*>(&sW[n * SW_STRIDE + k4]) = tv;
    }

    // ---- gather: warp w handles local rows [w*8, w*8+8); lane owns a float4
    const float4* x4 = reinterpret_cast<const float4*>(x);
#pragma unroll
    for (int rr = 0; rr < 8; rr++) {
        int lr   = w * 8 + rr;
        int node = row0 + lr;
        float4 acc = make_float4(0.f, 0.f, 0.f, 0.f);
        if (node < N_NODES) {
            float di = g_dinv[node];
            int beg  = g_offs[node];
            int cnt  = g_cnt[node];
            if (lane == 0) g_cnt[node] = 0;   // restore invariant for next call
            float4 v = x4[(size_t)node * 32 + lane];
            float dd = di * di;
            acc.x = v.x * dd; acc.y = v.y * dd; acc.z = v.z * dd; acc.w = v.w * dd;
            int j = 0;
            for (; j + 4 <= cnt; j += 4) {
                int2 e0 = g_edge[beg + j + 0];
                int2 e1 = g_edge[beg + j + 1];
                int2 e2 = g_edge[beg + j + 2];
                int2 e3 = g_edge[beg + j + 3];
                float n0 = di * __int_as_float(e0.y);
                float n1 = di * __int_as_float(e1.y);
                float n2 = di * __int_as_float(e2.y);
                float n3 = di * __int_as_float(e3.y);
                float4 v0 = x4[(size_t)e0.x * 32 + lane];
                float4 v1 = x4[(size_t)e1.x * 32 + lane];
                float4 v2 = x4[(size_t)e2.x * 32 + lane];
                float4 v3 = x4[(size_t)e3.x * 32 + lane];
                acc.x = fmaf(v0.x, n0, acc.x); acc.y = fmaf(v0.y, n0, acc.y);
                acc.z = fmaf(v0.z, n0, acc.z); acc.w = fmaf(v0.w, n0, acc.w);
                acc.x = fmaf(v1.x, n1, acc.x); acc.y = fmaf(v1.y, n1, acc.y);
                acc.z = fmaf(v1.z, n1, acc.z); acc.w = fmaf(v1.w, n1, acc.w);
                acc.x = fmaf(v2.x, n2, acc.x); acc.y = fmaf(v2.y, n2, acc.y);
                acc.z = fmaf(v2.z, n2, acc.z); acc.w = fmaf(v2.w, n2, acc.w);
                acc.x = fmaf(v3.x, n3, acc.x); acc.y = fmaf(v3.y, n3, acc.y);
                acc.z = fmaf(v3.z, n3, acc.z); acc.w = fmaf(v3.w, n3, acc.w);
            }
            for (; j < cnt; j++) {
                int2 e0 = g_edge[beg + j];
                float n0 = di * __int_as_float(e0.y);
                float4 v0 = x4[(size_t)e0.x * 32 + lane];
                acc.x = fmaf(v0.x, n0, acc.x); acc.y = fmaf(v0.y, n0, acc.y);
                acc.z = fmaf(v0.z, n0, acc.z); acc.w = fmaf(v0.w, n0, acc.w);
            }
        }
        uint4 st;
        st.x = f2tf32(acc.x); st.y = f2tf32(acc.y);
        st.z = f2tf32(acc.z); st.w = f2tf32(acc.w);
        *reinterpret_cast<uint4*>(&sA[lr * SA_STRIDE + lane * 4]) = st;
    }
    __syncthreads();

    // ---- tensor-core GEMM: warp tile M=16 (mw), N=64 (nw half) ----
    int mw = (w & 3) * 16;
    int nwBase = (w >> 2) * 64;
    int r  = lane >> 2;     // group id
    int cc = lane & 3;      // thread-in-group

    float c[8][4];
#pragma unroll
    for (int nt = 0; nt < 8; nt++)
#pragma unroll
        for (int q = 0; q < 4; q++) c[nt][q] = 0.0f;

    const uint32_t* Ar0 = &sA[(mw + r) * SA_STRIDE];
    const uint32_t* Ar1 = &sA[(mw + r + 8) * SA_STRIDE];

#pragma unroll
    for (int k0 = 0; k0 < 128; k0 += 8) {
        uint32_t a0 = Ar0[k0 + cc];
        uint32_t a1 = Ar1[k0 + cc];
        uint32_t a2 = Ar0[k0 + cc + 4];
        uint32_t a3 = Ar1[k0 + cc + 4];
#pragma unroll
        for (int nt = 0; nt < 8; nt++) {
            int n = nwBase + nt * 8 + r;
            uint32_t b0 = sW[n * SW_STRIDE + k0 + cc];
            uint32_t b1 = sW[n * SW_STRIDE + k0 + cc + 4];
            asm volatile(
                "mma.sync.aligned.m16n8k8.row.col.f32.tf32.tf32.f32 "
                "{%0,%1,%2,%3}, {%4,%5,%6,%7}, {%8,%9}, {%0,%1,%2,%3};\n"
                : "+f"(c[nt][0]), "+f"(c[nt][1]), "+f"(c[nt][2]), "+f"(c[nt][3])
                : "r"(a0), "r"(a1), "r"(a2), "r"(a3), "r"(b0), "r"(b1));
        }
    }

    // ---- epilogue: bias + relu + h store + w_lin partial dot ----
    int grow0 = row0 + mw + r;
    int grow1 = grow0 + 8;
    float pA = 0.f, pB = 0.f;
#pragma unroll
    for (int nt = 0; nt < 8; nt++) {
        int n = nwBase + nt * 8 + cc * 2;
        float bc0 = bconv[n], bc1 = bconv[n + 1];
        float wl0 = wlin[n],  wl1 = wlin[n + 1];
        float v00 = fmaxf(c[nt][0] + bc0, 0.f);
        float v01 = fmaxf(c[nt][1] + bc1, 0.f);
        float v10 = fmaxf(c[nt][2] + bc0, 0.f);
        float v11 = fmaxf(c[nt][3] + bc1, 0.f);
        pA = fmaf(v00, wl0, fmaf(v01, wl1, pA));
        pB = fmaf(v10, wl0, fmaf(v11, wl1, pB));
        if (grow0 < N_NODES)
            *reinterpret_cast<float2*>(&h_out[(size_t)grow0 * N_FEAT + n]) = make_float2(v00, v01);
        if (grow1 < N_NODES)
            *reinterpret_cast<float2*>(&h_out[(size_t)grow1 * N_FEAT + n]) = make_float2(v10, v11);
    }
    // reduce across the 4 threads of each group (cols of the same row)
    pA += __shfl_xor_sync(0xffffffffu, pA, 1);
    pA += __shfl_xor_sync(0xffffffffu, pA, 2);
    pB += __shfl_xor_sync(0xffffffffu, pB, 1);
    pB += __shfl_xor_sync(0xffffffffu, pB, 2);
    if (cc == 0) {
        atomicAdd(&sPart[mw + r], pA);       // two adds per row (n-halves):
        atomicAdd(&sPart[mw + r + 8], pB);   // order-independent in fp32
    }
    __syncthreads();
    if (tid < 64) {
        int gr = row0 + tid;
        if (gr < N_NODES)
            out[gr] = 1.0f / (1.0f + expf(-(sPart[tid] + blin[0])));
    }
}

// ---------------------------------------------------------------------------
extern "C" void kernel_launch(void* const* d_in, const int* in_sizes, int n_in,
                              void* d_out, int out_size) {
    const float* x  = (const float*)d_in[0];
    const int*   ei = (const int*)d_in[1];
    const float* Wc = (const float*)d_in[2];
    const float* bc = (const float*)d_in[3];
    const float* wl = (const float*)d_in[4];
    const float* bl = (const float*)d_in[5];

    float* out  = (float*)d_out;            // [N_NODES]
    float* hbuf = out + N_NODES;            // [N_NODES, 128]

    cudaFuncSetAttribute(k_fused, cudaFuncAttributeMaxDynamicSharedMemorySize,
                         SMEM_BYTES);

    k_hist<<<(N_EDGES + 255) / 256, 256>>>(ei);
    k_scan1<<<N_CHUNKS, SCAN_CHUNK>>>();
    k_scan3<<<N_CHUNKS, SCAN_CHUNK>>>();
    k_fill<<<(N_EDGES + 255) / 256, 256>>>(ei);
    k_fused<<<(N_NODES + 63) / 64, 256, SMEM_BYTES>>>(x, Wc, bc, wl, bl, out, hbuf);
}

// round 13
// speedup vs baseline: 1.0006x; 1.0006x over previous
#include <cuda_runtime.h>
#include <math.h>
#include <stdint.h>

#define N_NODES 100000
#define N_EDGES 640000
#define N_FEAT  128

#define SCAN_CHUNK 512
#define N_CHUNKS ((N_NODES + SCAN_CHUNK - 1) / SCAN_CHUNK)   // 196

// ---------------- scratch (device globals; zero-initialized at load) -------
__device__ int   g_cnt[N_NODES];        // invariant: zero at start of each call
__device__ int   g_offs[N_NODES];
__device__ int   g_cursor[N_NODES];
__device__ int2  g_edge[N_EDGES];       // (src, bits(dinv[src]))
__device__ int   g_partial[N_CHUNKS];
__device__ float g_dinv[N_NODES];

// fp32 -> tf32 (round-to-nearest) kept in a b32 register
__device__ __forceinline__ uint32_t f2tf32(float f) {
    uint32_t r;
    asm("cvt.rna.tf32.f32 %0, %1;" : "=r"(r) : "f"(f));
    return r;
}

// ---------------------------------------------------------------------------
// 1) histogram of edge destinations (g_cnt starts zeroed)
__global__ void k_hist(const int* __restrict__ ei) {
    int e = blockIdx.x * blockDim.x + threadIdx.x;
    if (e < N_EDGES) atomicAdd(&g_cnt[ei[N_EDGES + e]], 1);
}

// 2a) per-chunk exclusive scan, record chunk totals
__global__ __launch_bounds__(SCAN_CHUNK) void k_scan1() {
    __shared__ int s[SCAN_CHUNK];
    int t = threadIdx.x;
    int gid = blockIdx.x * SCAN_CHUNK + t;
    int v = (gid < N_NODES) ? g_cnt[gid] : 0;
    s[t] = v;
    __syncthreads();
#pragma unroll
    for (int d = 1; d < SCAN_CHUNK; d <<= 1) {
        int add = (t >= d) ? s[t - d] : 0;
        __syncthreads();
        s[t] += add;
        __syncthreads();
    }
    if (gid < N_NODES) g_offs[gid] = s[t] - v;
    if (t == SCAN_CHUNK - 1) g_partial[blockIdx.x] = s[t];
}

// 2b) add chunk base (each block reduces the partials itself); cursor; dinv
__global__ __launch_bounds__(SCAN_CHUNK) void k_scan3() {
    __shared__ int sp[16];
    int c = blockIdx.x;
    int t = threadIdx.x;
    int v = (t < c) ? g_partial[t] : 0;   // c < N_CHUNKS <= 512
#pragma unroll
    for (int o = 16; o; o >>= 1) v += __shfl_xor_sync(0xffffffffu, v, o);
    if ((t & 31) == 0) sp[t >> 5] = v;
    __syncthreads();
    if (t < 32) {
        int u = (t < 16) ? sp[t] : 0;
#pragma unroll
        for (int o = 8; o; o >>= 1) u += __shfl_xor_sync(0xffffffffu, u, o);
        if (t == 0) sp[0] = u;
    }
    __syncthreads();
    int base = sp[0];
    int i = c * SCAN_CHUNK + t;
    if (i < N_NODES) {
        int o = g_offs[i] + base;
        g_offs[i] = o;
        g_cursor[i] = o;
        g_dinv[i] = rsqrtf((float)(g_cnt[i] + 1));
    }
}

// 3) bucket fill: CSR-by-destination, store (src, dinv[src]) per slot
__global__ void k_fill(const int* __restrict__ ei) {
    int e = blockIdx.x * blockDim.x + threadIdx.x;
    if (e >= N_EDGES) return;
    int src = ei[e];
    int dst = ei[N_EDGES + e];
    int pos = atomicAdd(&g_cursor[dst], 1);
    g_edge[pos] = make_int2(src, __float_as_int(g_dinv[src]));
}

// ---------------------------------------------------------------------------
// 4) Fused gather + tf32 tensor-core GEMM + epilogue.
//    Block: 64 nodes, 256 threads (8 warps).
//    smem: A tile 64x128 (tf32), W 128x128 (tf32), 64 row-partials.
#define SA_STRIDE 132
#define SW_STRIDE 132
#define SMEM_A_OFF 0
#define SMEM_W_OFF (64 * SA_STRIDE)
#define SMEM_P_OFF (SMEM_W_OFF + 128 * SW_STRIDE)
#define SMEM_WORDS (SMEM_P_OFF + 64)
#define SMEM_BYTES (SMEM_WORDS * 4)

__global__ __launch_bounds__(256, 2) void k_fused(
    const float* __restrict__ x,
    const float* __restrict__ W,      // [128,128] row-major (out_feat, in_feat)
    const float* __restrict__ bconv,  // [128]
    const float* __restrict__ wlin,   // [128]
    const float* __restrict__ blin,   // [1]
    float* __restrict__ out,          // [N]
    float* __restrict__ h_out)        // [N,128]
{
    extern __shared__ uint32_t sm[];
    uint32_t* sA    = sm + SMEM_A_OFF;
    uint32_t* sW    = sm + SMEM_W_OFF;
    float*    sPart = (float*)(sm + SMEM_P_OFF);

    int tid  = threadIdx.x;
    int lane = tid & 31;
    int w    = tid >> 5;
    int row0 = blockIdx.x * 64;

    if (tid < 64) sPart[tid] = 0.0f;

    // ---- stage W into smem as tf32 (row-major [n][k], conflict-free) ----
    for (int i = tid; i < 128 * 32; i += 256) {
        int n  = i >> 5;
        int k4 = (i & 31) << 2;
        float4 wv = *reinterpret_cast<const float4*>(&W[n * N_FEAT + k4]);
        uint4 tv;
        tv.x = f2tf32(wv.x); tv.y = f2tf32(wv.y);
        tv.z = f2tf32(wv.z); tv.w = f2tf32(wv.w);
        *reinterpret_cast<uint4*>(&sW[n * SW_STRIDE + k4]) = tv;
    }

    // ---- gather: warp w handles local rows [w*8, w*8+8); lane owns a float4
    const float4* x4 = reinterpret_cast<const float4*>(x);
#pragma unroll
    for (int rr = 0; rr < 8; rr++) {
        int lr   = w * 8 + rr;
        int node = row0 + lr;
        float4 acc = make_float4(0.f, 0.f, 0.f, 0.f);
        if (node < N_NODES) {
            float di = g_dinv[node];
            int beg  = g_offs[node];
            int cnt  = g_cnt[node];
            if (lane == 0) g_cnt[node] = 0;   // restore invariant for next call
            float4 v = x4[(size_t)node * 32 + lane];
            float dd = di * di;
            acc.x = v.x * dd; acc.y = v.y * dd; acc.z = v.z * dd; acc.w = v.w * dd;
            int j = 0;
            for (; j + 4 <= cnt; j += 4) {
                int2 e0 = g_edge[beg + j + 0];
                int2 e1 = g_edge[beg + j + 1];
                int2 e2 = g_edge[beg + j + 2];
                int2 e3 = g_edge[beg + j + 3];
                float n0 = di * __int_as_float(e0.y);
                float n1 = di * __int_as_float(e1.y);
                float n2 = di * __int_as_float(e2.y);
                float n3 = di * __int_as_float(e3.y);
                float4 v0 = x4[(size_t)e0.x * 32 + lane];
                float4 v1 = x4[(size_t)e1.x * 32 + lane];
                float4 v2 = x4[(size_t)e2.x * 32 + lane];
                float4 v3 = x4[(size_t)e3.x * 32 + lane];
                acc.x = fmaf(v0.x, n0, acc.x); acc.y = fmaf(v0.y, n0, acc.y);
                acc.z = fmaf(v0.z, n0, acc.z); acc.w = fmaf(v0.w, n0, acc.w);
                acc.x = fmaf(v1.x, n1, acc.x); acc.y = fmaf(v1.y, n1, acc.y);
                acc.z = fmaf(v1.z, n1, acc.z); acc.w = fmaf(v1.w, n1, acc.w);
                acc.x = fmaf(v2.x, n2, acc.x); acc.y = fmaf(v2.y, n2, acc.y);
                acc.z = fmaf(v2.z, n2, acc.z); acc.w = fmaf(v2.w, n2, acc.w);
                acc.x = fmaf(v3.x, n3, acc.x); acc.y = fmaf(v3.y, n3, acc.y);
                acc.z = fmaf(v3.z, n3, acc.z); acc.w = fmaf(v3.w, n3, acc.w);
            }
            for (; j < cnt; j++) {
                int2 e0 = g_edge[beg + j];
                float n0 = di * __int_as_float(e0.y);
                float4 v0 = x4[(size_t)e0.x * 32 + lane];
                acc.x = fmaf(v0.x, n0, acc.x); acc.y = fmaf(v0.y, n0, acc.y);
                acc.z = fmaf(v0.z, n0, acc.z); acc.w = fmaf(v0.w, n0, acc.w);
            }
        }
        uint4 st;
        st.x = f2tf32(acc.x); st.y = f2tf32(acc.y);
        st.z = f2tf32(acc.z); st.w = f2tf32(acc.w);
        *reinterpret_cast<uint4*>(&sA[lr * SA_STRIDE + lane * 4]) = st;
    }
    __syncthreads();

    // ---- tensor-core GEMM: warp tile M=16 (mw), N=64 (nw half) ----
    int mw = (w & 3) * 16;
    int nwBase = (w >> 2) * 64;
    int r  = lane >> 2;     // group id
    int cc = lane & 3;      // thread-in-group

    float c[8][4];
#pragma unroll
    for (int nt = 0; nt < 8; nt++)
#pragma unroll
        for (int q = 0; q < 4; q++) c[nt][q] = 0.0f;

    const uint32_t* Ar0 = &sA[(mw + r) * SA_STRIDE];
    const uint32_t* Ar1 = &sA[(mw + r + 8) * SA_STRIDE];

#pragma unroll
    for (int k0 = 0; k0 < 128; k0 += 8) {
        uint32_t a0 = Ar0[k0 + cc];
        uint32_t a1 = Ar1[k0 + cc];
        uint32_t a2 = Ar0[k0 + cc + 4];
        uint32_t a3 = Ar1[k0 + cc + 4];
#pragma unroll
        for (int nt = 0; nt < 8; nt++) {
            int n = nwBase + nt * 8 + r;
            uint32_t b0 = sW[n * SW_STRIDE + k0 + cc];
            uint32_t b1 = sW[n * SW_STRIDE + k0 + cc + 4];
            asm volatile(
                "mma.sync.aligned.m16n8k8.row.col.f32.tf32.tf32.f32 "
                "{%0,%1,%2,%3}, {%4,%5,%6,%7}, {%8,%9}, {%0,%1,%2,%3};\n"
                : "+f"(c[nt][0]), "+f"(c[nt][1]), "+f"(c[nt][2]), "+f"(c[nt][3])
                : "r"(a0), "r"(a1), "r"(a2), "r"(a3), "r"(b0), "r"(b1));
        }
    }

    // ---- epilogue: bias + relu + h store + w_lin partial dot ----
    int grow0 = row0 + mw + r;
    int grow1 = grow0 + 8;
    float pA = 0.f, pB = 0.f;
#pragma unroll
    for (int nt = 0; nt < 8; nt++) {
        int n = nwBase + nt * 8 + cc * 2;
        float bc0 = bconv[n], bc1 = bconv[n + 1];
        float wl0 = wlin[n],  wl1 = wlin[n + 1];
        float v00 = fmaxf(c[nt][0] + bc0, 0.f);
        float v01 = fmaxf(c[nt][1] + bc1, 0.f);
        float v10 = fmaxf(c[nt][2] + bc0, 0.f);
        float v11 = fmaxf(c[nt][3] + bc1, 0.f);
        pA = fmaf(v00, wl0, fmaf(v01, wl1, pA));
        pB = fmaf(v10, wl0, fmaf(v11, wl1, pB));
        if (grow0 < N_NODES)
            *reinterpret_cast<float2*>(&h_out[(size_t)grow0 * N_FEAT + n]) = make_float2(v00, v01);
        if (grow1 < N_NODES)
            *reinterpret_cast<float2*>(&h_out[(size_t)grow1 * N_FEAT + n]) = make_float2(v10, v11);
    }
    // reduce across the 4 threads of each group (cols of the same row)
    pA += __shfl_xor_sync(0xffffffffu, pA, 1);
    pA += __shfl_xor_sync(0xffffffffu, pA, 2);
    pB += __shfl_xor_sync(0xffffffffu, pB, 1);
    pB += __shfl_xor_sync(0xffffffffu, pB, 2);
    if (cc == 0) {
        atomicAdd(&sPart[mw + r], pA);       // two adds per row (n-halves):
        atomicAdd(&sPart[mw + r + 8], pB);   // order-independent in fp32
    }
    __syncthreads();
    if (tid < 64) {
        int gr = row0 + tid;
        if (gr < N_NODES)
            out[gr] = 1.0f / (1.0f + expf(-(sPart[tid] + blin[0])));
    }
}

// ---------------------------------------------------------------------------
extern "C" void kernel_launch(void* const* d_in, const int* in_sizes, int n_in,
                              void* d_out, int out_size) {
    const float* x  = (const float*)d_in[0];
    const int*   ei = (const int*)d_in[1];
    const float* Wc = (const float*)d_in[2];
    const float* bc = (const float*)d_in[3];
    const float* wl = (const float*)d_in[4];
    const float* bl = (const float*)d_in[5];

    float* out  = (float*)d_out;            // [N_NODES]
    float* hbuf = out + N_NODES;            // [N_NODES, 128]

    cudaFuncSetAttribute(k_fused, cudaFuncAttributeMaxDynamicSharedMemorySize,
                         SMEM_BYTES);

    k_hist<<<(N_EDGES + 255) / 256, 256>>>(ei);
    k_scan1<<<N_CHUNKS, SCAN_CHUNK>>>();
    k_scan3<<<N_CHUNKS, SCAN_CHUNK>>>();
    k_fill<<<(N_EDGES + 255) / 256, 256>>>(ei);
    k_fused<<<(N_NODES + 63) / 64, 256, SMEM_BYTES>>>(x, Wc, bc, wl, bl, out, hbuf);
}

// round 14
// speedup vs baseline: 1.3316x; 1.3308x over previous
#include <cuda_runtime.h>
#include <math.h>
#include <stdint.h>

#define N_NODES 100000
#define N_EDGES 640000
#define N_FEAT  128

#define SCAN_CHUNK 512
#define N_CHUNKS ((N_NODES + SCAN_CHUNK - 1) / SCAN_CHUNK)   // 196

// ---------------- scratch (device globals; zero-initialized at load) -------
__device__ int   g_cnt[N_NODES];        // invariant: zero at entry of each call
__device__ int   g_offs[N_NODES];
__device__ int   g_cursor[N_NODES];
__device__ int   g_bucket[N_EDGES];     // src per CSR slot
__device__ int   g_partial[N_CHUNKS];
__device__ float g_dinv[N_NODES];
__device__ float g_tmp[(size_t)N_NODES * N_FEAT];

// fp32 -> tf32 (round-to-nearest) kept in a b32 register
__device__ __forceinline__ uint32_t f2tf32(float f) {
    uint32_t r;
    asm("cvt.rna.tf32.f32 %0, %1;" : "=r"(r) : "f"(f));
    return r;
}

// ---------------------------------------------------------------------------
// 1) histogram of edge destinations (g_cnt zeroed by invariant)
__global__ void k_hist(const int* __restrict__ ei) {
    int e = blockIdx.x * blockDim.x + threadIdx.x;
    if (e < N_EDGES) atomicAdd(&g_cnt[ei[N_EDGES + e]], 1);
}

// 2a) per-chunk exclusive scan, record chunk totals
__global__ __launch_bounds__(SCAN_CHUNK) void k_scan1() {
    __shared__ int s[SCAN_CHUNK];
    int t = threadIdx.x;
    int gid = blockIdx.x * SCAN_CHUNK + t;
    int v = (gid < N_NODES) ? g_cnt[gid] : 0;
    s[t] = v;
    __syncthreads();
#pragma unroll
    for (int d = 1; d < SCAN_CHUNK; d <<= 1) {
        int add = (t >= d) ? s[t - d] : 0;
        __syncthreads();
        s[t] += add;
        __syncthreads();
    }
    if (gid < N_NODES) g_offs[gid] = s[t] - v;
    if (t == SCAN_CHUNK - 1) g_partial[blockIdx.x] = s[t];
}

// 2b) add chunk base (each block reduces partials itself); cursor; dinv
__global__ __launch_bounds__(SCAN_CHUNK) void k_scan3() {
    __shared__ int sp[16];
    int c = blockIdx.x;
    int t = threadIdx.x;
    int v = (t < c) ? g_partial[t] : 0;   // c < N_CHUNKS <= 512
#pragma unroll
    for (int o = 16; o; o >>= 1) v += __shfl_xor_sync(0xffffffffu, v, o);
    if ((t & 31) == 0) sp[t >> 5] = v;
    __syncthreads();
    if (t < 32) {
        int u = (t < 16) ? sp[t] : 0;
#pragma unroll
        for (int o = 8; o; o >>= 1) u += __shfl_xor_sync(0xffffffffu, u, o);
        if (t == 0) sp[0] = u;
    }
    __syncthreads();
    int base = sp[0];
    int i = c * SCAN_CHUNK + t;
    if (i < N_NODES) {
        int o = g_offs[i] + base;
        g_offs[i] = o;
        g_cursor[i] = o;
        g_dinv[i] = rsqrtf((float)(g_cnt[i] + 1));
    }
}

// 3) bucket fill: CSR-by-destination (src only, 4B stores)
__global__ void k_fill(const int* __restrict__ ei) {
    int e = blockIdx.x * blockDim.x + threadIdx.x;
    if (e >= N_EDGES) return;
    int dst = ei[N_EDGES + e];
    int pos = atomicAdd(&g_cursor[dst], 1);
    g_bucket[pos] = ei[e];
}

// 4) gather: warp per destination node; lane owns one float4 of the 128-row.
//    Also restores g_cnt[node]=0 for the next replay.
__global__ __launch_bounds__(256) void k_gather(const float* __restrict__ x) {
    int t = blockIdx.x * blockDim.x + threadIdx.x;
    int node = t >> 5;
    int lane = t & 31;
    if (node >= N_NODES) return;

    const float4* x4 = reinterpret_cast<const float4*>(x);
    float di = g_dinv[node];
    int beg = g_offs[node];
    int cnt = g_cnt[node];
    if (lane == 0) g_cnt[node] = 0;      // restore invariant (after all lanes read)

    float4 v = x4[(size_t)node * 32 + lane];
    float dd = di * di;
    float4 acc;
    acc.x = v.x * dd; acc.y = v.y * dd; acc.z = v.z * dd; acc.w = v.w * dd;

    int j = 0;
    for (; j + 4 <= cnt; j += 4) {
        int s0 = g_bucket[beg + j + 0];
        int s1 = g_bucket[beg + j + 1];
        int s2 = g_bucket[beg + j + 2];
        int s3 = g_bucket[beg + j + 3];
        float n0 = di * g_dinv[s0];
        float n1 = di * g_dinv[s1];
        float n2 = di * g_dinv[s2];
        float n3 = di * g_dinv[s3];
        float4 v0 = x4[(size_t)s0 * 32 + lane];
        float4 v1 = x4[(size_t)s1 * 32 + lane];
        float4 v2 = x4[(size_t)s2 * 32 + lane];
        float4 v3 = x4[(size_t)s3 * 32 + lane];
        acc.x = fmaf(v0.x, n0, acc.x); acc.y = fmaf(v0.y, n0, acc.y);
        acc.z = fmaf(v0.z, n0, acc.z); acc.w = fmaf(v0.w, n0, acc.w);
        acc.x = fmaf(v1.x, n1, acc.x); acc.y = fmaf(v1.y, n1, acc.y);
        acc.z = fmaf(v1.z, n1, acc.z); acc.w = fmaf(v1.w, n1, acc.w);
        acc.x = fmaf(v2.x, n2, acc.x); acc.y = fmaf(v2.y, n2, acc.y);
        acc.z = fmaf(v2.z, n2, acc.z); acc.w = fmaf(v2.w, n2, acc.w);
        acc.x = fmaf(v3.x, n3, acc.x); acc.y = fmaf(v3.y, n3, acc.y);
        acc.z = fmaf(v3.z, n3, acc.z); acc.w = fmaf(v3.w, n3, acc.w);
    }
    for (; j < cnt; j++) {
        int s0 = g_bucket[beg + j];
        float n0 = di * g_dinv[s0];
        float4 v0 = x4[(size_t)s0 * 32 + lane];
        acc.x = fmaf(v0.x, n0, acc.x); acc.y = fmaf(v0.y, n0, acc.y);
        acc.z = fmaf(v0.z, n0, acc.z); acc.w = fmaf(v0.w, n0, acc.w);
    }
    reinterpret_cast<float4*>(g_tmp)[(size_t)node * 32 + lane] = acc;
}

// ---------------------------------------------------------------------------
// 5) tf32 tensor-core GEMM + epilogue.
//    Block: 64 rows, 256 threads (8 warps); warp tile M=16, N=64.
//    h   = relu(tmp @ W^T + b_conv)   -> h_out [N,128]
//    out = sigmoid(h . w_lin + b_lin) -> out  [N]
#define SA_STRIDE 132
#define SW_STRIDE 132
#define SMEM_A_OFF 0
#define SMEM_W_OFF (64 * SA_STRIDE)
#define SMEM_P_OFF (SMEM_W_OFF + 128 * SW_STRIDE)
#define SMEM_WORDS (SMEM_P_OFF + 64)
#define SMEM_BYTES (SMEM_WORDS * 4)

__global__ __launch_bounds__(256, 2) void k_gemm(
    const float* __restrict__ W,      // [128,128] row-major (out_feat, in_feat)
    const float* __restrict__ bconv,  // [128]
    const float* __restrict__ wlin,   // [128]
    const float* __restrict__ blin,   // [1]
    float* __restrict__ out,          // [N]
    float* __restrict__ h_out)        // [N,128]
{
    extern __shared__ uint32_t sm[];
    uint32_t* sA    = sm + SMEM_A_OFF;
    uint32_t* sW    = sm + SMEM_W_OFF;
    float*    sPart = (float*)(sm + SMEM_P_OFF);

    int tid  = threadIdx.x;
    int lane = tid & 31;
    int w    = tid >> 5;
    int row0 = blockIdx.x * 64;

    if (tid < 64) sPart[tid] = 0.0f;

    // stage W (tf32) — row-major [n][k]
    for (int i = tid; i < 128 * 32; i += 256) {
        int n  = i >> 5;
        int k4 = (i & 31) << 2;
        float4 wv = *reinterpret_cast<const float4*>(&W[n * N_FEAT + k4]);
        uint4 tv;
        tv.x = f2tf32(wv.x); tv.y = f2tf32(wv.y);
        tv.z = f2tf32(wv.z); tv.w = f2tf32(wv.w);
        *reinterpret_cast<uint4*>(&sW[n * SW_STRIDE + k4]) = tv;
    }
    // stage A tile (tf32) from g_tmp — 64 x 128
    for (int i = tid; i < 64 * 32; i += 256) {
        int r  = i >> 5;
        int k4 = (i & 31) << 2;
        int grow = row0 + r;
        float4 av = make_float4(0.f, 0.f, 0.f, 0.f);
        if (grow < N_NODES)
            av = *reinterpret_cast<const float4*>(&g_tmp[(size_t)grow * N_FEAT + k4]);
        uint4 tv;
        tv.x = f2tf32(av.x); tv.y = f2tf32(av.y);
        tv.z = f2tf32(av.z); tv.w = f2tf32(av.w);
        *reinterpret_cast<uint4*>(&sA[r * SA_STRIDE + k4]) = tv;
    }
    __syncthreads();

    // warp tile: M rows [mw, mw+16), N cols [nwBase, nwBase+64)
    int mw = (w & 3) * 16;
    int nwBase = (w >> 2) * 64;
    int r  = lane >> 2;     // 0..7
    int cc = lane & 3;      // 0..3

    float c[8][4];
#pragma unroll
    for (int nt = 0; nt < 8; nt++)
#pragma unroll
        for (int q = 0; q < 4; q++) c[nt][q] = 0.0f;

    const uint32_t* Ar0 = &sA[(mw + r) * SA_STRIDE];
    const uint32_t* Ar1 = &sA[(mw + r + 8) * SA_STRIDE];

#pragma unroll
    for (int k0 = 0; k0 < 128; k0 += 8) {
        uint32_t a0 = Ar0[k0 + cc];
        uint32_t a1 = Ar1[k0 + cc];
        uint32_t a2 = Ar0[k0 + cc + 4];
        uint32_t a3 = Ar1[k0 + cc + 4];
#pragma unroll
        for (int nt = 0; nt < 8; nt++) {
            int n = nwBase + nt * 8 + r;
            uint32_t b0 = sW[n * SW_STRIDE + k0 + cc];
            uint32_t b1 = sW[n * SW_STRIDE + k0 + cc + 4];
            asm volatile(
                "mma.sync.aligned.m16n8k8.row.col.f32.tf32.tf32.f32 "
                "{%0,%1,%2,%3}, {%4,%5,%6,%7}, {%8,%9}, {%0,%1,%2,%3};\n"
                : "+f"(c[nt][0]), "+f"(c[nt][1]), "+f"(c[nt][2]), "+f"(c[nt][3])
                : "r"(a0), "r"(a1), "r"(a2), "r"(a3), "r"(b0), "r"(b1));
        }
    }

    // epilogue: bias + relu + h store + w_lin partial dot
    int grow0 = row0 + mw + r;
    int grow1 = grow0 + 8;
    float pA = 0.f, pB = 0.f;
#pragma unroll
    for (int nt = 0; nt < 8; nt++) {
        int n = nwBase + nt * 8 + cc * 2;
        float bc0 = bconv[n], bc1 = bconv[n + 1];
        float wl0 = wlin[n],  wl1 = wlin[n + 1];
        float v00 = fmaxf(c[nt][0] + bc0, 0.f);
        float v01 = fmaxf(c[nt][1] + bc1, 0.f);
        float v10 = fmaxf(c[nt][2] + bc0, 0.f);
        float v11 = fmaxf(c[nt][3] + bc1, 0.f);
        pA = fmaf(v00, wl0, fmaf(v01, wl1, pA));
        pB = fmaf(v10, wl0, fmaf(v11, wl1, pB));
        if (grow0 < N_NODES)
            *reinterpret_cast<float2*>(&h_out[(size_t)grow0 * N_FEAT + n]) = make_float2(v00, v01);
        if (grow1 < N_NODES)
            *reinterpret_cast<float2*>(&h_out[(size_t)grow1 * N_FEAT + n]) = make_float2(v10, v11);
    }
    pA += __shfl_xor_sync(0xffffffffu, pA, 1);
    pA += __shfl_xor_sync(0xffffffffu, pA, 2);
    pB += __shfl_xor_sync(0xffffffffu, pB, 1);
    pB += __shfl_xor_sync(0xffffffffu, pB, 2);
    if (cc == 0) {
        atomicAdd(&sPart[mw + r], pA);
        atomicAdd(&sPart[mw + r + 8], pB);
    }
    __syncthreads();
    if (tid < 64) {
        int gr = row0 + tid;
        if (gr < N_NODES)
            out[gr] = 1.0f / (1.0f + expf(-(sPart[tid] + blin[0])));
    }
}

// ---------------------------------------------------------------------------
extern "C" void kernel_launch(void* const* d_in, const int* in_sizes, int n_in,
                              void* d_out, int out_size) {
    const float* x  = (const float*)d_in[0];
    const int*   ei = (const int*)d_in[1];
    const float* Wc = (const float*)d_in[2];
    const float* bc = (const float*)d_in[3];
    const float* wl = (const float*)d_in[4];
    const float* bl = (const float*)d_in[5];

    float* out  = (float*)d_out;            // [N_NODES]
    float* hbuf = out + N_NODES;            // [N_NODES, 128]

    cudaFuncSetAttribute(k_gemm, cudaFuncAttributeMaxDynamicSharedMemorySize,
                         SMEM_BYTES);

    k_hist<<<(N_EDGES + 255) / 256, 256>>>(ei);
    k_scan1<<<N_CHUNKS, SCAN_CHUNK>>>();
    k_scan3<<<N_CHUNKS, SCAN_CHUNK>>>();
    k_fill<<<(N_EDGES + 255) / 256, 256>>>(ei);
    {
        long long t = (long long)N_NODES * 32;
        k_gather<<<(unsigned)((t + 255) / 256), 256>>>(x);
    }
    k_gemm<<<(N_NODES + 63) / 64, 256, SMEM_BYTES>>>(Wc, bc, wl, bl, out, hbuf);
}